// round 8
// baseline (speedup 1.0000x reference)
#include <cuda_runtime.h>
#include <cuda_bf16.h>
#include <cstdint>

#define T_TOK 8192
#define D_DIM 1024
#define F_DIM 3584
#define N_EXP 8
#define N_ASSIGN (T_TOK * 2)
#define BM 128
#define BK 32
#define MAX_TILES (N_ASSIGN / BM + N_EXP)  // 136

// ---------------- scratch (static __device__, allocation-free) ----------------
__device__ float g_h[(size_t)N_ASSIGN * F_DIM];   // SwiGLU intermediate
__device__ int   g_rowtok[N_ASSIGN];
__device__ float g_roww[N_ASSIGN];
__device__ int   g_route_e[N_ASSIGN];
__device__ float g_route_w[N_ASSIGN];
__device__ int   g_cnt[N_EXP];                    // zero-init at load; re-zeroed by k_scan
__device__ int   g_cur[N_EXP];
__device__ int   g_off[N_EXP + 1];
__device__ int   g_tile_e[MAX_TILES];
__device__ int   g_tile_r0[MAX_TILES];
__device__ int   g_tile_rend[MAX_TILES];
__device__ int   g_ntiles;

// ---------------- helpers ----------------
__device__ __forceinline__ uint32_t f2tfu(float f) {
    uint32_t r;
    asm("cvt.rna.tf32.f32 %0, %1;" : "=r"(r) : "f"(f));
    return r;
}

__device__ __forceinline__ void mma_tf32(float c[4], uint32_t a0, uint32_t a1,
                                         uint32_t a2, uint32_t a3,
                                         uint32_t b0, uint32_t b1) {
    asm volatile(
        "mma.sync.aligned.m16n8k8.row.col.f32.tf32.tf32.f32 "
        "{%0,%1,%2,%3}, {%4,%5,%6,%7}, {%8,%9}, {%0,%1,%2,%3};\n"
        : "+f"(c[0]), "+f"(c[1]), "+f"(c[2]), "+f"(c[3])
        : "r"(a0), "r"(a1), "r"(a2), "r"(a3), "r"(b0), "r"(b1));
}

__device__ __forceinline__ void cp16(void* s, const void* g) {
    uint32_t sa = (uint32_t)__cvta_generic_to_shared(s);
    asm volatile("cp.async.cg.shared.global [%0], [%1], 16;\n" :: "r"(sa), "l"(g));
}
__device__ __forceinline__ void cp16p(void* s, const void* g, bool p) {
    uint32_t sa = (uint32_t)__cvta_generic_to_shared(s);
    int b = p ? 16 : 0;
    asm volatile("cp.async.cg.shared.global [%0], [%1], 16, %2;\n" :: "r"(sa), "l"(g), "r"(b));
}
__device__ __forceinline__ void cp_commit() {
    asm volatile("cp.async.commit_group;\n" ::: "memory");
}
template <int N>
__device__ __forceinline__ void cp_wait() {
    asm volatile("cp.async.wait_group %0;\n" :: "n"(N) : "memory");
}

// ---------------- router / scan / scatter / zero ----------------
__global__ void k_router(const float* __restrict__ x, const float* __restrict__ gw,
                         float* __restrict__ logits_out) {
    int t = blockIdx.x;
    int tid = threadIdx.x;                 // 256 threads
    const float* xr = x + (size_t)t * D_DIM;

    float acc[N_EXP];
#pragma unroll
    for (int e = 0; e < N_EXP; e++) acc[e] = 0.f;

    for (int j = tid; j < D_DIM; j += 256) {
        float xv = xr[j];
#pragma unroll
        for (int e = 0; e < N_EXP; e++) acc[e] += xv * gw[e * D_DIM + j];
    }
#pragma unroll
    for (int e = 0; e < N_EXP; e++)
#pragma unroll
        for (int o = 16; o > 0; o >>= 1)
            acc[e] += __shfl_xor_sync(0xffffffffu, acc[e], o);

    __shared__ float wsum[8][N_EXP];
    __shared__ float sl[N_EXP];
    int wid = tid >> 5, lane = tid & 31;
    if (lane == 0) {
#pragma unroll
        for (int e = 0; e < N_EXP; e++) wsum[wid][e] = acc[e];
    }
    __syncthreads();
    if (tid < N_EXP) {
        float s = 0.f;
#pragma unroll
        for (int w = 0; w < 8; w++) s += wsum[w][tid];
        sl[tid] = s;
        logits_out[(size_t)t * N_EXP + tid] = s;
    }
    __syncthreads();
    if (tid == 0) {
        float l[N_EXP];
#pragma unroll
        for (int e = 0; e < N_EXP; e++) l[e] = sl[e];
        int i0 = 0;
#pragma unroll
        for (int e = 1; e < N_EXP; e++) if (l[e] > l[i0]) i0 = e;
        int i1 = (i0 == 0) ? 1 : 0;
#pragma unroll
        for (int e = 0; e < N_EXP; e++) if (e != i0 && l[e] > l[i1]) i1 = e;
        float r = __expf(l[i1] - l[i0]);
        float w0 = 1.f / (1.f + r);
        float w1 = r / (1.f + r);
        g_route_e[2 * t] = i0;  g_route_w[2 * t] = w0;
        g_route_e[2 * t + 1] = i1; g_route_w[2 * t + 1] = w1;
        atomicAdd(&g_cnt[i0], 1);
        atomicAdd(&g_cnt[i1], 1);
    }
}

__global__ void k_scan() {
    if (blockIdx.x == 0 && threadIdx.x == 0) {
        int off = 0;
        for (int e = 0; e < N_EXP; e++) { g_off[e] = off; off += g_cnt[e]; g_cur[e] = 0; }
        g_off[N_EXP] = off;
        int nt = 0;
        for (int e = 0; e < N_EXP; e++) {
            int c = g_cnt[e], r0 = g_off[e];
            int m = (c + BM - 1) / BM;
            for (int i = 0; i < m; i++) {
                g_tile_e[nt] = e;
                g_tile_r0[nt] = r0 + i * BM;
                g_tile_rend[nt] = r0 + c;
                nt++;
            }
        }
        g_ntiles = nt;
        // reset counters for the NEXT kernel_launch call (graph replay)
        for (int e = 0; e < N_EXP; e++) g_cnt[e] = 0;
    }
}

__global__ void k_scatter() {
    int t = blockIdx.x * blockDim.x + threadIdx.x;
    if (t < T_TOK) {
#pragma unroll
        for (int k = 0; k < 2; k++) {
            int e = g_route_e[2 * t + k];
            int p = g_off[e] + atomicAdd(&g_cur[e], 1);
            g_rowtok[p] = t;
            g_roww[p] = g_route_w[2 * t + k];
        }
    }
}

__global__ void k_zero(float4* p, int n4) {
    int stride = gridDim.x * blockDim.x;
    for (int i = blockIdx.x * blockDim.x + threadIdx.x; i < n4; i += stride)
        p[i] = make_float4(0.f, 0.f, 0.f, 0.f);
}

// ---------------- GEMM1: H = silu(Xg @ W1) * (Xg @ W3), tf32, 3-stage ----------------
// block tile: 128 x 64 (both w1 & w3) x K=1024; one barrier per k-tile
#define G1_STAGE (128 * 36 + 2 * 32 * 68)          // floats per stage: 35840B
#define G1_SMEM  (3 * G1_STAGE * 4)
__global__ __launch_bounds__(256, 2)
void k_gemm1(const float* __restrict__ x, const float* __restrict__ w1g,
             const float* __restrict__ w3g) {
    int tile = blockIdx.x;
    if (tile >= g_ntiles) return;
    int e = g_tile_e[tile], row0 = g_tile_r0[tile], rend = g_tile_rend[tile];
    int n0 = blockIdx.y * 64;

    extern __shared__ float dyn[];
    float (*sA)[BM][36]     = (float (*)[BM][36])dyn;                   // [3][128][36]
    float (*sB)[2][BK][68]  = (float (*)[2][BK][68])(dyn + 3 * BM * 36);// [3][2][32][68]

    __shared__ int sTok[BM];

    int tid = threadIdx.x;
    if (tid < BM) {
        int r = row0 + tid;
        sTok[tid] = (r < rend) ? g_rowtok[r] : -1;
    }
    __syncthreads();

    const float* wb0 = w1g + (size_t)e * D_DIM * F_DIM;
    const float* wb1 = w3g + (size_t)e * D_DIM * F_DIM;

    int wid = tid >> 5, lane = tid & 31;
    int wm = (wid & 3) * 32, wn = (wid >> 2) * 32;

    int arow[4], ac4[4];
    const float* asrc[4];
    bool apred[4];
#pragma unroll
    for (int i = 0; i < 4; i++) {
        int idx = i * 256 + tid;
        arow[i] = idx >> 3; ac4[i] = idx & 7;
        int tok = sTok[arow[i]];
        asrc[i] = (tok >= 0) ? (x + (size_t)tok * D_DIM + ac4[i] * 4) : x;
        apred[i] = (tok >= 0);
    }

    auto issue = [&](int kt, int buf) {
#pragma unroll
        for (int i = 0; i < 4; i++)
            cp16p(&sA[buf][arow[i]][ac4[i] * 4], asrc[i] + kt * BK, apred[i]);
#pragma unroll
        for (int m = 0; m < 2; m++) {
            const float* wb = m ? wb1 : wb0;
#pragma unroll
            for (int i = 0; i < 2; i++) {
                int idx = i * 256 + tid;
                int kr = idx >> 4, c4 = idx & 15;
                cp16(&sB[buf][m][kr][c4 * 4],
                     wb + (size_t)(kt * BK + kr) * F_DIM + n0 + c4 * 4);
            }
        }
        cp_commit();
    };

    float accP[2][4][4], accQ[2][4][4];
#pragma unroll
    for (int i = 0; i < 2; i++)
#pragma unroll
        for (int j = 0; j < 4; j++)
#pragma unroll
            for (int k = 0; k < 4; k++) { accP[i][j][k] = 0.f; accQ[i][j][k] = 0.f; }

    const int NK = D_DIM / BK;             // 32
    issue(0, 0);
    issue(1, 1);

    for (int kt = 0; kt < NK; kt++) {
        int buf = kt - (kt / 3) * 3;       // kt % 3
        if (kt < NK - 1) cp_wait<1>(); else cp_wait<0>();
        __syncthreads();                    // all warps past compute(kt-1); buffer (kt+2)%3 free
        if (kt + 2 < NK) issue(kt + 2, (kt + 2) - ((kt + 2) / 3) * 3);

#pragma unroll
        for (int ks = 0; ks < 4; ks++) {
            int kk = ks * 8;
            uint32_t a[2][4];
#pragma unroll
            for (int mf = 0; mf < 2; mf++) {
                int rb = wm + mf * 16;
                a[mf][0] = f2tfu(sA[buf][rb + (lane >> 2)][kk + (lane & 3)]);
                a[mf][1] = f2tfu(sA[buf][rb + 8 + (lane >> 2)][kk + (lane & 3)]);
                a[mf][2] = f2tfu(sA[buf][rb + (lane >> 2)][kk + 4 + (lane & 3)]);
                a[mf][3] = f2tfu(sA[buf][rb + 8 + (lane >> 2)][kk + 4 + (lane & 3)]);
            }
#pragma unroll
            for (int nf = 0; nf < 4; nf++) {
                int cb = wn + nf * 8 + (lane >> 2);
                uint32_t p0 = f2tfu(sB[buf][0][kk + (lane & 3)][cb]);
                uint32_t p1 = f2tfu(sB[buf][0][kk + 4 + (lane & 3)][cb]);
                uint32_t q0 = f2tfu(sB[buf][1][kk + (lane & 3)][cb]);
                uint32_t q1 = f2tfu(sB[buf][1][kk + 4 + (lane & 3)][cb]);
#pragma unroll
                for (int mf = 0; mf < 2; mf++) {
                    mma_tf32(accP[mf][nf], a[mf][0], a[mf][1], a[mf][2], a[mf][3], p0, p1);
                    mma_tf32(accQ[mf][nf], a[mf][0], a[mf][1], a[mf][2], a[mf][3], q0, q1);
                }
            }
        }
    }

    // epilogue: h = silu(p) * q
#pragma unroll
    for (int mf = 0; mf < 2; mf++) {
#pragma unroll
        for (int half = 0; half < 2; half++) {
            int rl = wm + mf * 16 + (lane >> 2) + half * 8;
            int r = row0 + rl;
            if (r < rend) {
#pragma unroll
                for (int nf = 0; nf < 4; nf++) {
                    int col = n0 + wn + nf * 8 + (lane & 3) * 2;
                    float p0 = accP[mf][nf][half * 2], p1 = accP[mf][nf][half * 2 + 1];
                    float q0 = accQ[mf][nf][half * 2], q1 = accQ[mf][nf][half * 2 + 1];
                    float h0 = (p0 / (1.f + __expf(-p0))) * q0;
                    float h1 = (p1 / (1.f + __expf(-p1))) * q1;
                    *(float2*)(g_h + (size_t)r * F_DIM + col) = make_float2(h0, h1);
                }
            }
        }
    }
}

// ---------------- GEMM2: Y = H @ W2[e], tf32, 3-stage, scatter-add ----------------
#define G2_STAGE (128 * 36 + 32 * 132)             // floats per stage: 35328B
#define G2_SMEM  (3 * G2_STAGE * 4)
__global__ __launch_bounds__(256, 2)
void k_gemm2(const float* __restrict__ w2g, float* __restrict__ out) {
    int tile = blockIdx.x;
    if (tile >= g_ntiles) return;
    int e = g_tile_e[tile], row0 = g_tile_r0[tile], rend = g_tile_rend[tile];
    int n0 = blockIdx.y * 128;

    extern __shared__ float dyn[];
    float (*sA)[BM][36]  = (float (*)[BM][36])dyn;                      // [3][128][36]
    float (*sB)[BK][132] = (float (*)[BK][132])(dyn + 3 * BM * 36);     // [3][32][132]

    __shared__ int   sTok[BM];
    __shared__ float sW[BM];

    int tid = threadIdx.x;
    if (tid < BM) {
        int r = row0 + tid;
        sTok[tid] = (r < rend) ? g_rowtok[r] : 0;
        sW[tid]   = (r < rend) ? g_roww[r] : 0.f;
    }
    __syncthreads();

    const float* wb = w2g + (size_t)e * F_DIM * D_DIM;
    int wid = tid >> 5, lane = tid & 31;
    int wm = (wid & 1) * 64, wn = (wid >> 1) * 32;

    int arow[4], ac4[4];
    bool apred[4];
#pragma unroll
    for (int i = 0; i < 4; i++) {
        int idx = i * 256 + tid;
        arow[i] = idx >> 3; ac4[i] = idx & 7;
        apred[i] = (row0 + arow[i]) < rend;
    }

    auto issue = [&](int kt, int buf) {
#pragma unroll
        for (int i = 0; i < 4; i++)
            cp16p(&sA[buf][arow[i]][ac4[i] * 4],
                  g_h + (size_t)(row0 + arow[i]) * F_DIM + kt * BK + ac4[i] * 4,
                  apred[i]);
#pragma unroll
        for (int i = 0; i < 4; i++) {
            int idx = i * 256 + tid;
            int kr = idx >> 5, c4 = idx & 31;
            cp16(&sB[buf][kr][c4 * 4],
                 wb + (size_t)(kt * BK + kr) * D_DIM + n0 + c4 * 4);
        }
        cp_commit();
    };

    float acc[4][4][4];
#pragma unroll
    for (int i = 0; i < 4; i++)
#pragma unroll
        for (int j = 0; j < 4; j++)
#pragma unroll
            for (int k = 0; k < 4; k++) acc[i][j][k] = 0.f;

    const int NK = F_DIM / BK;             // 112
    issue(0, 0);
    issue(1, 1);

    for (int kt = 0; kt < NK; kt++) {
        int buf = kt - (kt / 3) * 3;
        if (kt < NK - 1) cp_wait<1>(); else cp_wait<0>();
        __syncthreads();
        if (kt + 2 < NK) issue(kt + 2, (kt + 2) - ((kt + 2) / 3) * 3);

#pragma unroll
        for (int ks = 0; ks < 4; ks++) {
            int kk = ks * 8;
            uint32_t a[4][4];
#pragma unroll
            for (int mf = 0; mf < 4; mf++) {
                int rb = wm + mf * 16;
                a[mf][0] = f2tfu(sA[buf][rb + (lane >> 2)][kk + (lane & 3)]);
                a[mf][1] = f2tfu(sA[buf][rb + 8 + (lane >> 2)][kk + (lane & 3)]);
                a[mf][2] = f2tfu(sA[buf][rb + (lane >> 2)][kk + 4 + (lane & 3)]);
                a[mf][3] = f2tfu(sA[buf][rb + 8 + (lane >> 2)][kk + 4 + (lane & 3)]);
            }
#pragma unroll
            for (int nf = 0; nf < 4; nf++) {
                int cb = wn + nf * 8 + (lane >> 2);
                uint32_t b0 = f2tfu(sB[buf][kk + (lane & 3)][cb]);
                uint32_t b1 = f2tfu(sB[buf][kk + 4 + (lane & 3)][cb]);
#pragma unroll
                for (int mf = 0; mf < 4; mf++)
                    mma_tf32(acc[mf][nf], a[mf][0], a[mf][1], a[mf][2], a[mf][3], b0, b1);
            }
        }
    }

#pragma unroll
    for (int mf = 0; mf < 4; mf++) {
#pragma unroll
        for (int half = 0; half < 2; half++) {
            int rl = wm + mf * 16 + (lane >> 2) + half * 8;
            int r = row0 + rl;
            if (r < rend) {
                int tok = sTok[rl];
                float s = sW[rl];
                float* op = out + (size_t)tok * D_DIM;
#pragma unroll
                for (int nf = 0; nf < 4; nf++) {
                    int col = n0 + wn + nf * 8 + (lane & 3) * 2;
                    atomicAdd(op + col,     acc[mf][nf][half * 2] * s);
                    atomicAdd(op + col + 1, acc[mf][nf][half * 2 + 1] * s);
                }
            }
        }
    }
}

// ---------------- entry ----------------
extern "C" void kernel_launch(void* const* d_in, const int* in_sizes, int n_in,
                              void* d_out, int out_size) {
    const float* x  = (const float*)d_in[0];   // hidden_states [4,2048,1024]
    const float* gw = (const float*)d_in[1];   // gate_w [8,1024]
    const float* w1 = (const float*)d_in[2];   // [8,1024,3584]
    const float* w3 = (const float*)d_in[3];   // [8,1024,3584]
    const float* w2 = (const float*)d_in[4];   // [8,3584,1024]

    float* out = (float*)d_out;                         // [T*D] moe output
    float* logits = out + (size_t)T_TOK * D_DIM;        // [T*E] router logits

    static bool attr_set = false;
    if (!attr_set) {
        cudaFuncSetAttribute(k_gemm1, cudaFuncAttributeMaxDynamicSharedMemorySize, G1_SMEM);
        cudaFuncSetAttribute(k_gemm2, cudaFuncAttributeMaxDynamicSharedMemorySize, G2_SMEM);
        attr_set = true;
    }

    // g_cnt starts zeroed (load-time zero-init; re-zeroed at tail of k_scan each call)
    k_router<<<T_TOK, 256>>>(x, gw, logits);            // launch 0
    k_scan<<<1, 1>>>();                                 // launch 1
    k_scatter<<<T_TOK / 256, 256>>>();                  // launch 2
    dim3 g1(MAX_TILES, F_DIM / 64);
    k_gemm1<<<g1, 256, G1_SMEM>>>(x, w1, w3);           // launch 3  <- ncu capture target
    k_zero<<<2048, 256>>>((float4*)out, (T_TOK * D_DIM) / 4);   // launch 4
    dim3 g2(MAX_TILES, D_DIM / 128);
    k_gemm2<<<g2, 256, G2_SMEM>>>(w2, out);             // launch 5
}

// round 9
// speedup vs baseline: 2.6255x; 2.6255x over previous
#include <cuda_runtime.h>
#include <cuda_fp16.h>
#include <cstdint>

#define T_TOK 8192
#define D_DIM 1024
#define F_DIM 3584
#define N_EXP 8
#define N_ASSIGN (T_TOK * 2)
#define BM 128
#define BK 32
#define MAX_TILES (N_ASSIGN / BM + N_EXP)  // 136

// ---------------- scratch (static __device__, allocation-free) ----------------
__device__ __half g_xh [(size_t)T_TOK * D_DIM];           // x, fp16 [t][d]
__device__ __half g_w1t[(size_t)N_EXP * F_DIM * D_DIM];   // w1^T fp16 [e][n][k]
__device__ __half g_w3t[(size_t)N_EXP * F_DIM * D_DIM];   // w3^T fp16 [e][n][k]
__device__ __half g_w2t[(size_t)N_EXP * D_DIM * F_DIM];   // w2^T fp16 [e][d][f]
__device__ __half g_hh [(size_t)N_ASSIGN * F_DIM];        // SwiGLU out, fp16
__device__ int   g_rowtok[N_ASSIGN];
__device__ float g_roww[N_ASSIGN];
__device__ int   g_route_e[N_ASSIGN];
__device__ float g_route_w[N_ASSIGN];
__device__ int   g_cnt[N_EXP];                 // zero at load; re-zeroed each call
__device__ int   g_off[N_EXP + 1];
__device__ int   g_tile_e[MAX_TILES];
__device__ int   g_tile_r0[MAX_TILES];
__device__ int   g_tile_rend[MAX_TILES];
__device__ int   g_ntiles;

// ---------------- helpers ----------------
__device__ __forceinline__ void mma_f16(float c[4], uint32_t a0, uint32_t a1,
                                        uint32_t a2, uint32_t a3,
                                        uint32_t b0, uint32_t b1) {
    asm volatile(
        "mma.sync.aligned.m16n8k16.row.col.f32.f16.f16.f32 "
        "{%0,%1,%2,%3}, {%4,%5,%6,%7}, {%8,%9}, {%0,%1,%2,%3};\n"
        : "+f"(c[0]), "+f"(c[1]), "+f"(c[2]), "+f"(c[3])
        : "r"(a0), "r"(a1), "r"(a2), "r"(a3), "r"(b0), "r"(b1));
}
__device__ __forceinline__ uint32_t ldh2(const __half* p) {
    return *reinterpret_cast<const uint32_t*>(p);
}
__device__ __forceinline__ void cp16(void* s, const void* g) {
    uint32_t sa = (uint32_t)__cvta_generic_to_shared(s);
    asm volatile("cp.async.cg.shared.global [%0], [%1], 16;\n" :: "r"(sa), "l"(g));
}
__device__ __forceinline__ void cp16p(void* s, const void* g, bool p) {
    uint32_t sa = (uint32_t)__cvta_generic_to_shared(s);
    int b = p ? 16 : 0;
    asm volatile("cp.async.cg.shared.global [%0], [%1], 16, %2;\n" :: "r"(sa), "l"(g), "r"(b));
}
__device__ __forceinline__ void cp_commit() {
    asm volatile("cp.async.commit_group;\n" ::: "memory");
}
template <int N>
__device__ __forceinline__ void cp_wait() {
    asm volatile("cp.async.wait_group %0;\n" :: "n"(N) : "memory");
}

// ---------------- prepass: convert/transpose everything to fp16 ----------------
// blocks: [0,28672) w1^T, [28672,57344) w3^T, [57344,86016) w2^T, [86016,87040) x-copy
__global__ void k_prep(const float* __restrict__ x,  const float* __restrict__ w1,
                       const float* __restrict__ w3, const float* __restrict__ w2) {
    __shared__ float t[32][33];
    int bid = blockIdx.x, tid = threadIdx.x;
    if (bid < 86016) {
        int which = bid / 28672;
        int r = bid % 28672;
        const float* src; __half* dst; int K, N;
        if (which == 0)      { src = w1; dst = g_w1t; K = D_DIM; N = F_DIM; }
        else if (which == 1) { src = w3; dst = g_w3t; K = D_DIM; N = F_DIM; }
        else                 { src = w2; dst = g_w2t; K = F_DIM; N = D_DIM; }
        int per_e = (K / 32) * (N / 32);           // 3584 for all three
        int e = r / per_e, rr = r % per_e;
        int nt = rr % (N / 32), kt = rr / (N / 32);
        int n0 = nt * 32, k0 = kt * 32;
        int tx = tid & 31, ty = tid >> 5;          // (32, 8)
        const float* s = src + (size_t)e * K * N;
        __half* d = dst + (size_t)e * N * K;
        for (int i = ty; i < 32; i += 8)
            t[i][tx] = s[(size_t)(k0 + i) * N + n0 + tx];
        __syncthreads();
        for (int i = ty; i < 32; i += 8)
            d[(size_t)(n0 + i) * K + k0 + tx] = __float2half_rn(t[tx][i]);
    } else {
        int base = (bid - 86016) * 8192;
        for (int j = tid; j < 8192; j += 256)
            g_xh[base + j] = __float2half_rn(x[base + j]);
    }
}

// ---------------- router ----------------
__global__ void k_router(const float* __restrict__ x, const float* __restrict__ gw,
                         float* __restrict__ logits_out) {
    int t = blockIdx.x, tid = threadIdx.x;
    const float* xr = x + (size_t)t * D_DIM;
    float acc[N_EXP];
#pragma unroll
    for (int e = 0; e < N_EXP; e++) acc[e] = 0.f;
    for (int j = tid; j < D_DIM; j += 256) {
        float xv = xr[j];
#pragma unroll
        for (int e = 0; e < N_EXP; e++) acc[e] += xv * gw[e * D_DIM + j];
    }
#pragma unroll
    for (int e = 0; e < N_EXP; e++)
#pragma unroll
        for (int o = 16; o > 0; o >>= 1)
            acc[e] += __shfl_xor_sync(0xffffffffu, acc[e], o);
    __shared__ float wsum[8][N_EXP];
    __shared__ float sl[N_EXP];
    int wid = tid >> 5, lane = tid & 31;
    if (lane == 0)
#pragma unroll
        for (int e = 0; e < N_EXP; e++) wsum[wid][e] = acc[e];
    __syncthreads();
    if (tid < N_EXP) {
        float s = 0.f;
#pragma unroll
        for (int w = 0; w < 8; w++) s += wsum[w][tid];
        sl[tid] = s;
        logits_out[(size_t)t * N_EXP + tid] = s;
    }
    __syncthreads();
    if (tid == 0) {
        float l[N_EXP];
#pragma unroll
        for (int e = 0; e < N_EXP; e++) l[e] = sl[e];
        int i0 = 0;
#pragma unroll
        for (int e = 1; e < N_EXP; e++) if (l[e] > l[i0]) i0 = e;
        int i1 = (i0 == 0) ? 1 : 0;
#pragma unroll
        for (int e = 0; e < N_EXP; e++) if (e != i0 && l[e] > l[i1]) i1 = e;
        float r = __expf(l[i1] - l[i0]);
        g_route_e[2 * t] = i0;     g_route_w[2 * t] = 1.f / (1.f + r);
        g_route_e[2 * t + 1] = i1; g_route_w[2 * t + 1] = r / (1.f + r);
        atomicAdd(&g_cnt[i0], 1);
        atomicAdd(&g_cnt[i1], 1);
    }
}

// ---------------- scan + scatter, one block (smem atomics) ----------------
__global__ void k_scan_scatter() {
    __shared__ int scur[N_EXP];
    int tid = threadIdx.x;
    if (tid == 0) {
        int off = 0;
        for (int e = 0; e < N_EXP; e++) { g_off[e] = off; off += g_cnt[e]; }
        g_off[N_EXP] = off;
        int nt = 0;
        for (int e = 0; e < N_EXP; e++) {
            int c = g_cnt[e], r0 = g_off[e];
            for (int i = 0; i < (c + BM - 1) / BM; i++) {
                g_tile_e[nt] = e; g_tile_r0[nt] = r0 + i * BM; g_tile_rend[nt] = r0 + c; nt++;
            }
        }
        g_ntiles = nt;
        for (int e = 0; e < N_EXP; e++) g_cnt[e] = 0;   // reset for next call
    }
    if (tid < N_EXP) scur[tid] = 0;
    __syncthreads();
    for (int t = tid; t < T_TOK; t += 256) {
#pragma unroll
        for (int k = 0; k < 2; k++) {
            int e = g_route_e[2 * t + k];
            int p = g_off[e] + atomicAdd(&scur[e], 1);
            g_rowtok[p] = t;
            g_roww[p] = g_route_w[2 * t + k];
        }
    }
}

__global__ void k_zero(float4* p, int n4) {
    int stride = gridDim.x * blockDim.x;
    for (int i = blockIdx.x * blockDim.x + threadIdx.x; i < n4; i += stride)
        p[i] = make_float4(0.f, 0.f, 0.f, 0.f);
}

// ---------------- GEMM1: H = silu(Xg@W1) * (Xg@W3), fp16 m16n8k16, 2-stage ----------------
// stage: A [128][40] half + B [2][64][40] half = 20480B; 2 stages = 40960B
#define G1_SMEM (2 * (128 * 40 + 2 * 64 * 40) * 2)
__global__ __launch_bounds__(256, 2)
void k_gemm1() {
    int tile = blockIdx.x;
    if (tile >= g_ntiles) return;
    int e = g_tile_e[tile], row0 = g_tile_r0[tile], rend = g_tile_rend[tile];
    int n0 = blockIdx.y * 64;

    extern __shared__ __half dyn[];
    __half (*sA)[128][40]    = (__half (*)[128][40])dyn;                  // [2][128][40]
    __half (*sB)[2][64][40]  = (__half (*)[2][64][40])(dyn + 2 * 128 * 40);

    __shared__ int sTok[BM];
    int tid = threadIdx.x;
    if (tid < BM) {
        int r = row0 + tid;
        sTok[tid] = (r < rend) ? g_rowtok[r] : -1;
    }
    __syncthreads();

    const __half* w1t = g_w1t + (size_t)e * F_DIM * D_DIM;
    const __half* w3t = g_w3t + (size_t)e * F_DIM * D_DIM;

    int wid = tid >> 5, lane = tid & 31;
    int wm = (wid & 3) * 32, wn = (wid >> 2) * 32;

    // per-thread staging coordinates (2 A-chunks, 2 B-chunks)
    int arow[2], ac[2];
    const __half* asrc[2];
    bool apred[2];
#pragma unroll
    for (int i = 0; i < 2; i++) {
        int id = i * 256 + tid;            // 0..511
        arow[i] = id >> 2; ac[i] = id & 3;
        int tok = sTok[arow[i]];
        asrc[i] = g_xh + (size_t)(tok < 0 ? 0 : tok) * D_DIM + ac[i] * 8;
        apred[i] = (tok >= 0);
    }

    auto issue = [&](int kt, int buf) {
#pragma unroll
        for (int i = 0; i < 2; i++)
            cp16p(&sA[buf][arow[i]][ac[i] * 8], asrc[i] + kt * BK, apred[i]);
#pragma unroll
        for (int i = 0; i < 2; i++) {
            int id = i * 256 + tid;
            int mat = id >> 8, rem = id & 255;
            int row = rem >> 2, c = rem & 3;
            const __half* wt = mat ? w3t : w1t;
            cp16(&sB[buf][mat][row][c * 8],
                 wt + (size_t)(n0 + row) * D_DIM + kt * BK + c * 8);
        }
        cp_commit();
    };

    float accP[2][4][4], accQ[2][4][4];
#pragma unroll
    for (int i = 0; i < 2; i++)
#pragma unroll
        for (int j = 0; j < 4; j++)
#pragma unroll
            for (int k = 0; k < 4; k++) { accP[i][j][k] = 0.f; accQ[i][j][k] = 0.f; }

    const int NK = D_DIM / BK;             // 32
    issue(0, 0);

    for (int kt = 0; kt < NK; kt++) {
        int buf = kt & 1;
        if (kt + 1 < NK) { issue(kt + 1, (kt + 1) & 1); cp_wait<1>(); }
        else             { cp_wait<0>(); }
        __syncthreads();

#pragma unroll
        for (int ks = 0; ks < 2; ks++) {
            int kb = ks * 16 + (lane & 3) * 2;
            uint32_t a[2][4];
#pragma unroll
            for (int mf = 0; mf < 2; mf++) {
                int rb = wm + mf * 16 + (lane >> 2);
                a[mf][0] = ldh2(&sA[buf][rb][kb]);
                a[mf][1] = ldh2(&sA[buf][rb + 8][kb]);
                a[mf][2] = ldh2(&sA[buf][rb][kb + 8]);
                a[mf][3] = ldh2(&sA[buf][rb + 8][kb + 8]);
            }
#pragma unroll
            for (int nf = 0; nf < 4; nf++) {
                int cb = wn + nf * 8 + (lane >> 2);
                uint32_t p0 = ldh2(&sB[buf][0][cb][kb]);
                uint32_t p1 = ldh2(&sB[buf][0][cb][kb + 8]);
                uint32_t q0 = ldh2(&sB[buf][1][cb][kb]);
                uint32_t q1 = ldh2(&sB[buf][1][cb][kb + 8]);
#pragma unroll
                for (int mf = 0; mf < 2; mf++) {
                    mma_f16(accP[mf][nf], a[mf][0], a[mf][1], a[mf][2], a[mf][3], p0, p1);
                    mma_f16(accQ[mf][nf], a[mf][0], a[mf][1], a[mf][2], a[mf][3], q0, q1);
                }
            }
        }
        __syncthreads();
    }

    // epilogue: h = silu(p) * q -> fp16 pair store
#pragma unroll
    for (int mf = 0; mf < 2; mf++) {
#pragma unroll
        for (int half_ = 0; half_ < 2; half_++) {
            int rl = wm + mf * 16 + (lane >> 2) + half_ * 8;
            int r = row0 + rl;
            if (r < rend) {
#pragma unroll
                for (int nf = 0; nf < 4; nf++) {
                    int col = n0 + wn + nf * 8 + (lane & 3) * 2;
                    float p0 = accP[mf][nf][half_ * 2], p1 = accP[mf][nf][half_ * 2 + 1];
                    float q0 = accQ[mf][nf][half_ * 2], q1 = accQ[mf][nf][half_ * 2 + 1];
                    float h0 = (p0 / (1.f + __expf(-p0))) * q0;
                    float h1 = (p1 / (1.f + __expf(-p1))) * q1;
                    __half2 hv; hv.x = __float2half_rn(h0); hv.y = __float2half_rn(h1);
                    *(__half2*)(g_hh + (size_t)r * F_DIM + col) = hv;
                }
            }
        }
    }
}

// ---------------- GEMM2: Y = H @ W2[e], fp16 m16n8k16, 2-stage, scatter-add ----------------
// stage: A [128][40] + B [128][40] = 20480B; 2 stages = 40960B
#define G2_SMEM (2 * (128 * 40 + 128 * 40) * 2)
__global__ __launch_bounds__(256, 2)
void k_gemm2(float* __restrict__ out) {
    int tile = blockIdx.x;
    if (tile >= g_ntiles) return;
    int e = g_tile_e[tile], row0 = g_tile_r0[tile], rend = g_tile_rend[tile];
    int n0 = blockIdx.y * 128;

    extern __shared__ __half dyn[];
    __half (*sA)[128][40] = (__half (*)[128][40])dyn;                     // [2][128][40]
    __half (*sB)[128][40] = (__half (*)[128][40])(dyn + 2 * 128 * 40);

    __shared__ int   sTok[BM];
    __shared__ float sW[BM];
    int tid = threadIdx.x;
    if (tid < BM) {
        int r = row0 + tid;
        sTok[tid] = (r < rend) ? g_rowtok[r] : 0;
        sW[tid]   = (r < rend) ? g_roww[r] : 0.f;
    }
    __syncthreads();

    const __half* w2t = g_w2t + (size_t)e * D_DIM * F_DIM;
    int wid = tid >> 5, lane = tid & 31;
    int wm = (wid & 1) * 64, wn = (wid >> 1) * 32;

    int arow[2], ac[2];
    bool apred[2];
#pragma unroll
    for (int i = 0; i < 2; i++) {
        int id = i * 256 + tid;
        arow[i] = id >> 2; ac[i] = id & 3;
        apred[i] = (row0 + arow[i]) < rend;
    }

    auto issue = [&](int kt, int buf) {
#pragma unroll
        for (int i = 0; i < 2; i++)
            cp16p(&sA[buf][arow[i]][ac[i] * 8],
                  g_hh + (size_t)(row0 + arow[i]) * F_DIM + kt * BK + ac[i] * 8,
                  apred[i]);
#pragma unroll
        for (int i = 0; i < 2; i++) {
            int id = i * 256 + tid;
            int row = id >> 2, c = id & 3;
            cp16(&sB[buf][row][c * 8],
                 w2t + (size_t)(n0 + row) * F_DIM + kt * BK + c * 8);
        }
        cp_commit();
    };

    float acc[4][4][4];
#pragma unroll
    for (int i = 0; i < 4; i++)
#pragma unroll
        for (int j = 0; j < 4; j++)
#pragma unroll
            for (int k = 0; k < 4; k++) acc[i][j][k] = 0.f;

    const int NK = F_DIM / BK;             // 112
    issue(0, 0);

    for (int kt = 0; kt < NK; kt++) {
        int buf = kt & 1;
        if (kt + 1 < NK) { issue(kt + 1, (kt + 1) & 1); cp_wait<1>(); }
        else             { cp_wait<0>(); }
        __syncthreads();

#pragma unroll
        for (int ks = 0; ks < 2; ks++) {
            int kb = ks * 16 + (lane & 3) * 2;
            uint32_t a[4][4];
#pragma unroll
            for (int mf = 0; mf < 4; mf++) {
                int rb = wm + mf * 16 + (lane >> 2);
                a[mf][0] = ldh2(&sA[buf][rb][kb]);
                a[mf][1] = ldh2(&sA[buf][rb + 8][kb]);
                a[mf][2] = ldh2(&sA[buf][rb][kb + 8]);
                a[mf][3] = ldh2(&sA[buf][rb + 8][kb + 8]);
            }
#pragma unroll
            for (int nf = 0; nf < 4; nf++) {
                int cb = wn + nf * 8 + (lane >> 2);
                uint32_t b0 = ldh2(&sB[buf][cb][kb]);
                uint32_t b1 = ldh2(&sB[buf][cb][kb + 8]);
#pragma unroll
                for (int mf = 0; mf < 4; mf++)
                    mma_f16(acc[mf][nf], a[mf][0], a[mf][1], a[mf][2], a[mf][3], b0, b1);
            }
        }
        __syncthreads();
    }

    // epilogue: out[tok, col] += weight * acc (exactly 2 adds/element -> deterministic)
#pragma unroll
    for (int mf = 0; mf < 4; mf++) {
#pragma unroll
        for (int half_ = 0; half_ < 2; half_++) {
            int rl = wm + mf * 16 + (lane >> 2) + half_ * 8;
            int r = row0 + rl;
            if (r < rend) {
                int tok = sTok[rl];
                float s = sW[rl];
                float* op = out + (size_t)tok * D_DIM;
#pragma unroll
                for (int nf = 0; nf < 4; nf++) {
                    int col = n0 + wn + nf * 8 + (lane & 3) * 2;
                    atomicAdd(op + col,     acc[mf][nf][half_ * 2] * s);
                    atomicAdd(op + col + 1, acc[mf][nf][half_ * 2 + 1] * s);
                }
            }
        }
    }
}

// ---------------- entry ----------------
extern "C" void kernel_launch(void* const* d_in, const int* in_sizes, int n_in,
                              void* d_out, int out_size) {
    const float* x  = (const float*)d_in[0];   // [4,2048,1024]
    const float* gw = (const float*)d_in[1];   // [8,1024]
    const float* w1 = (const float*)d_in[2];   // [8,1024,3584]
    const float* w3 = (const float*)d_in[3];   // [8,1024,3584]
    const float* w2 = (const float*)d_in[4];   // [8,3584,1024]

    float* out = (float*)d_out;
    float* logits = out + (size_t)T_TOK * D_DIM;

    static bool attr_set = false;
    if (!attr_set) {
        cudaFuncSetAttribute(k_gemm1, cudaFuncAttributeMaxDynamicSharedMemorySize, G1_SMEM);
        cudaFuncSetAttribute(k_gemm2, cudaFuncAttributeMaxDynamicSharedMemorySize, G2_SMEM);
        attr_set = true;
    }

    k_prep<<<87040, 256>>>(x, w1, w3, w2);              // launch 0 (~85us)
    k_router<<<T_TOK, 256>>>(x, gw, logits);            // launch 1
    k_scan_scatter<<<1, 256>>>();                       // launch 2
    dim3 g1(MAX_TILES, F_DIM / 64);
    k_gemm1<<<g1, 256, G1_SMEM>>>();                    // launch 3 <- ncu target
    k_zero<<<2048, 256>>>((float4*)out, (T_TOK * D_DIM) / 4);   // launch 4
    dim3 g2(MAX_TILES, D_DIM / 128);
    k_gemm2<<<g2, 256, G2_SMEM>>>(out);                 // launch 5
}

// round 10
// speedup vs baseline: 2.9033x; 1.1058x over previous
#include <cuda_runtime.h>
#include <cuda_fp16.h>
#include <cstdint>

#define T_TOK 8192
#define D_DIM 1024
#define F_DIM 3584
#define N_EXP 8
#define N_ASSIGN (T_TOK * 2)
#define BM 128
#define BK 32
#define MAX_TILES (N_ASSIGN / BM + N_EXP)  // 136

// ---------------- scratch (static __device__, allocation-free) ----------------
__device__ __half g_xh [(size_t)T_TOK * D_DIM];           // x, fp16 [t][d]
__device__ __half g_w1t[(size_t)N_EXP * F_DIM * D_DIM];   // w1^T fp16 [e][n][k]
__device__ __half g_w3t[(size_t)N_EXP * F_DIM * D_DIM];   // w3^T fp16 [e][n][k]
__device__ __half g_w2t[(size_t)N_EXP * D_DIM * F_DIM];   // w2^T fp16 [e][d][f]
__device__ __half g_hh [(size_t)N_ASSIGN * F_DIM];        // SwiGLU out, fp16
__device__ int   g_rowtok[N_ASSIGN];
__device__ float g_roww[N_ASSIGN];
__device__ int   g_route_e[N_ASSIGN];
__device__ float g_route_w[N_ASSIGN];
__device__ int   g_cnt[N_EXP];                 // zero at load; re-zeroed each call
__device__ int   g_off[N_EXP + 1];
__device__ int   g_tile_e[MAX_TILES];
__device__ int   g_tile_r0[MAX_TILES];
__device__ int   g_tile_rend[MAX_TILES];
__device__ int   g_ntiles;

// ---------------- helpers ----------------
__device__ __forceinline__ void mma_f16(float c[4], uint32_t a0, uint32_t a1,
                                        uint32_t a2, uint32_t a3,
                                        uint32_t b0, uint32_t b1) {
    asm volatile(
        "mma.sync.aligned.m16n8k16.row.col.f32.f16.f16.f32 "
        "{%0,%1,%2,%3}, {%4,%5,%6,%7}, {%8,%9}, {%0,%1,%2,%3};\n"
        : "+f"(c[0]), "+f"(c[1]), "+f"(c[2]), "+f"(c[3])
        : "r"(a0), "r"(a1), "r"(a2), "r"(a3), "r"(b0), "r"(b1));
}
__device__ __forceinline__ void ldsm4(uint32_t r[4], uint32_t addr) {
    asm volatile("ldmatrix.sync.aligned.m8n8.x4.shared.b16 {%0,%1,%2,%3}, [%4];"
        : "=r"(r[0]), "=r"(r[1]), "=r"(r[2]), "=r"(r[3]) : "r"(addr));
}
__device__ __forceinline__ uint32_t s2u(const void* p) {
    return (uint32_t)__cvta_generic_to_shared(p);
}
__device__ __forceinline__ void cp16(void* s, const void* g) {
    uint32_t sa = (uint32_t)__cvta_generic_to_shared(s);
    asm volatile("cp.async.cg.shared.global [%0], [%1], 16;\n" :: "r"(sa), "l"(g));
}
__device__ __forceinline__ void cp16p(void* s, const void* g, bool p) {
    uint32_t sa = (uint32_t)__cvta_generic_to_shared(s);
    int b = p ? 16 : 0;
    asm volatile("cp.async.cg.shared.global [%0], [%1], 16, %2;\n" :: "r"(sa), "l"(g), "r"(b));
}
__device__ __forceinline__ void cp_commit() {
    asm volatile("cp.async.commit_group;\n" ::: "memory");
}
template <int N>
__device__ __forceinline__ void cp_wait() {
    asm volatile("cp.async.wait_group %0;\n" :: "n"(N) : "memory");
}

// ---------------- prepass: convert/transpose everything to fp16 ----------------
__global__ void k_prep(const float* __restrict__ x,  const float* __restrict__ w1,
                       const float* __restrict__ w3, const float* __restrict__ w2) {
    __shared__ float t[32][33];
    int bid = blockIdx.x, tid = threadIdx.x;
    if (bid < 86016) {
        int which = bid / 28672;
        int r = bid % 28672;
        const float* src; __half* dst; int K, N;
        if (which == 0)      { src = w1; dst = g_w1t; K = D_DIM; N = F_DIM; }
        else if (which == 1) { src = w3; dst = g_w3t; K = D_DIM; N = F_DIM; }
        else                 { src = w2; dst = g_w2t; K = F_DIM; N = D_DIM; }
        int per_e = (K / 32) * (N / 32);           // 3584
        int e = r / per_e, rr = r % per_e;
        int nt = rr % (N / 32), kt = rr / (N / 32);
        int n0 = nt * 32, k0 = kt * 32;
        int tx = tid & 31, ty = tid >> 5;
        const float* s = src + (size_t)e * K * N;
        __half* d = dst + (size_t)e * N * K;
        for (int i = ty; i < 32; i += 8)
            t[i][tx] = s[(size_t)(k0 + i) * N + n0 + tx];
        __syncthreads();
        for (int i = ty; i < 32; i += 8)
            d[(size_t)(n0 + i) * K + k0 + tx] = __float2half_rn(t[tx][i]);
    } else {
        int base = (bid - 86016) * 8192;
        for (int j = tid; j < 8192; j += 256)
            g_xh[base + j] = __float2half_rn(x[base + j]);
    }
}

// ---------------- router ----------------
__global__ void k_router(const float* __restrict__ x, const float* __restrict__ gw,
                         float* __restrict__ logits_out) {
    int t = blockIdx.x, tid = threadIdx.x;
    const float* xr = x + (size_t)t * D_DIM;
    float acc[N_EXP];
#pragma unroll
    for (int e = 0; e < N_EXP; e++) acc[e] = 0.f;
    for (int j = tid; j < D_DIM; j += 256) {
        float xv = xr[j];
#pragma unroll
        for (int e = 0; e < N_EXP; e++) acc[e] += xv * gw[e * D_DIM + j];
    }
#pragma unroll
    for (int e = 0; e < N_EXP; e++)
#pragma unroll
        for (int o = 16; o > 0; o >>= 1)
            acc[e] += __shfl_xor_sync(0xffffffffu, acc[e], o);
    __shared__ float wsum[8][N_EXP];
    __shared__ float sl[N_EXP];
    int wid = tid >> 5, lane = tid & 31;
    if (lane == 0)
#pragma unroll
        for (int e = 0; e < N_EXP; e++) wsum[wid][e] = acc[e];
    __syncthreads();
    if (tid < N_EXP) {
        float s = 0.f;
#pragma unroll
        for (int w = 0; w < 8; w++) s += wsum[w][tid];
        sl[tid] = s;
        logits_out[(size_t)t * N_EXP + tid] = s;
    }
    __syncthreads();
    if (tid == 0) {
        float l[N_EXP];
#pragma unroll
        for (int e = 0; e < N_EXP; e++) l[e] = sl[e];
        int i0 = 0;
#pragma unroll
        for (int e = 1; e < N_EXP; e++) if (l[e] > l[i0]) i0 = e;
        int i1 = (i0 == 0) ? 1 : 0;
#pragma unroll
        for (int e = 0; e < N_EXP; e++) if (e != i0 && l[e] > l[i1]) i1 = e;
        float r = __expf(l[i1] - l[i0]);
        g_route_e[2 * t] = i0;     g_route_w[2 * t] = 1.f / (1.f + r);
        g_route_e[2 * t + 1] = i1; g_route_w[2 * t + 1] = r / (1.f + r);
        atomicAdd(&g_cnt[i0], 1);
        atomicAdd(&g_cnt[i1], 1);
    }
}

// ---------------- scan + scatter, one block ----------------
__global__ void k_scan_scatter() {
    __shared__ int scur[N_EXP];
    int tid = threadIdx.x;
    if (tid == 0) {
        int off = 0;
        for (int e = 0; e < N_EXP; e++) { g_off[e] = off; off += g_cnt[e]; }
        g_off[N_EXP] = off;
        int nt = 0;
        for (int e = 0; e < N_EXP; e++) {
            int c = g_cnt[e], r0 = g_off[e];
            for (int i = 0; i < (c + BM - 1) / BM; i++) {
                g_tile_e[nt] = e; g_tile_r0[nt] = r0 + i * BM; g_tile_rend[nt] = r0 + c; nt++;
            }
        }
        g_ntiles = nt;
        for (int e = 0; e < N_EXP; e++) g_cnt[e] = 0;
    }
    if (tid < N_EXP) scur[tid] = 0;
    __syncthreads();
    for (int t = tid; t < T_TOK; t += 256) {
#pragma unroll
        for (int k = 0; k < 2; k++) {
            int e = g_route_e[2 * t + k];
            int p = g_off[e] + atomicAdd(&scur[e], 1);
            g_rowtok[p] = t;
            g_roww[p] = g_route_w[2 * t + k];
        }
    }
}

__global__ void k_zero(float4* p, int n4) {
    int stride = gridDim.x * blockDim.x;
    for (int i = blockIdx.x * blockDim.x + threadIdx.x; i < n4; i += stride)
        p[i] = make_float4(0.f, 0.f, 0.f, 0.f);
}

// ---------------- GEMM1: H = silu(Xg@W1) * (Xg@W3), fp16 + ldmatrix ----------------
// smem bytes: A[2][128][40] = 20480, B[2][2][64][40] = 20480
#define G1_SMEM 40960
__global__ __launch_bounds__(256, 2)
void k_gemm1() {
    int tile = blockIdx.x;
    if (tile >= g_ntiles) return;
    int e = g_tile_e[tile], row0 = g_tile_r0[tile], rend = g_tile_rend[tile];
    int n0 = blockIdx.y * 64;

    extern __shared__ __half dyn[];
    __half (*sA)[128][40]    = (__half (*)[128][40])dyn;
    __half (*sB)[2][64][40]  = (__half (*)[2][64][40])(dyn + 2 * 128 * 40);
    uint32_t smemB = s2u(dyn);

    __shared__ int sTok[BM];
    int tid = threadIdx.x;
    if (tid < BM) {
        int r = row0 + tid;
        sTok[tid] = (r < rend) ? g_rowtok[r] : -1;
    }
    __syncthreads();

    const __half* w1t = g_w1t + (size_t)e * F_DIM * D_DIM;
    const __half* w3t = g_w3t + (size_t)e * F_DIM * D_DIM;

    int wid = tid >> 5, lane = tid & 31;
    int wm = (wid & 3) * 32, wn = (wid >> 2) * 32;

    // ldmatrix per-lane offsets (in halves): quad = lane>>3, i = lane&7
    uint32_t aoff = (((lane >> 3) & 1) * 8 + (lane & 7)) * 40 + (lane >> 4) * 8;
    uint32_t boff = ((lane >> 4) * 8 + (lane & 7)) * 40 + ((lane >> 3) & 1) * 8;

    int arow[2], ac[2];
    const __half* asrc[2];
    bool apred[2];
#pragma unroll
    for (int i = 0; i < 2; i++) {
        int id = i * 256 + tid;
        arow[i] = id >> 2; ac[i] = id & 3;
        int tok = sTok[arow[i]];
        asrc[i] = g_xh + (size_t)(tok < 0 ? 0 : tok) * D_DIM + ac[i] * 8;
        apred[i] = (tok >= 0);
    }

    auto issue = [&](int kt, int buf) {
#pragma unroll
        for (int i = 0; i < 2; i++)
            cp16p(&sA[buf][arow[i]][ac[i] * 8], asrc[i] + kt * BK, apred[i]);
#pragma unroll
        for (int i = 0; i < 2; i++) {
            int id = i * 256 + tid;
            int mat = id >> 8, rem = id & 255;
            int row = rem >> 2, c = rem & 3;
            const __half* wt = mat ? w3t : w1t;
            cp16(&sB[buf][mat][row][c * 8],
                 wt + (size_t)(n0 + row) * D_DIM + kt * BK + c * 8);
        }
        cp_commit();
    };

    float accP[2][4][4], accQ[2][4][4];
#pragma unroll
    for (int i = 0; i < 2; i++)
#pragma unroll
        for (int j = 0; j < 4; j++)
#pragma unroll
            for (int k = 0; k < 4; k++) { accP[i][j][k] = 0.f; accQ[i][j][k] = 0.f; }

    const int NK = D_DIM / BK;             // 32
    issue(0, 0);

    for (int kt = 0; kt < NK; kt++) {
        int buf = kt & 1;
        if (kt + 1 < NK) { issue(kt + 1, (kt + 1) & 1); cp_wait<1>(); }
        else             { cp_wait<0>(); }
        __syncthreads();

#pragma unroll
        for (int ks = 0; ks < 2; ks++) {
            uint32_t a[2][4];
#pragma unroll
            for (int mf = 0; mf < 2; mf++)
                ldsm4(a[mf], smemB + (buf * 5120 +                     // buf*128*40
                       (wm + mf * 16) * 40 + ks * 16 + aoff) * 2);
#pragma unroll
            for (int mat = 0; mat < 2; mat++) {
#pragma unroll
                for (int j = 0; j < 2; j++) {
                    uint32_t b[4];                                      // [b0 nf=2j, b1, b0 nf=2j+1, b1]
                    ldsm4(b, smemB + 20480 + ((buf * 2 + mat) * 2560 + // (64*40)
                           (wn + j * 16) * 40 + ks * 16 + boff) * 2);
#pragma unroll
                    for (int mf = 0; mf < 2; mf++) {
                        float* c0 = mat ? accQ[mf][2 * j]     : accP[mf][2 * j];
                        float* c1 = mat ? accQ[mf][2 * j + 1] : accP[mf][2 * j + 1];
                        mma_f16(c0, a[mf][0], a[mf][1], a[mf][2], a[mf][3], b[0], b[1]);
                        mma_f16(c1, a[mf][0], a[mf][1], a[mf][2], a[mf][3], b[2], b[3]);
                    }
                }
            }
        }
        __syncthreads();
    }

    // epilogue: h = silu(p) * q -> fp16 pair store
#pragma unroll
    for (int mf = 0; mf < 2; mf++) {
#pragma unroll
        for (int half_ = 0; half_ < 2; half_++) {
            int rl = wm + mf * 16 + (lane >> 2) + half_ * 8;
            int r = row0 + rl;
            if (r < rend) {
#pragma unroll
                for (int nf = 0; nf < 4; nf++) {
                    int col = n0 + wn + nf * 8 + (lane & 3) * 2;
                    float p0 = accP[mf][nf][half_ * 2], p1 = accP[mf][nf][half_ * 2 + 1];
                    float q0 = accQ[mf][nf][half_ * 2], q1 = accQ[mf][nf][half_ * 2 + 1];
                    float h0 = (p0 / (1.f + __expf(-p0))) * q0;
                    float h1 = (p1 / (1.f + __expf(-p1))) * q1;
                    __half2 hv; hv.x = __float2half_rn(h0); hv.y = __float2half_rn(h1);
                    *(__half2*)(g_hh + (size_t)r * F_DIM + col) = hv;
                }
            }
        }
    }
}

// ---------------- GEMM2: Y = H @ W2[e], fp16 + ldmatrix, scatter-add ----------------
// smem bytes: A[2][128][40] = 20480, B[2][128][40] = 20480
#define G2_SMEM 40960
__global__ __launch_bounds__(256, 2)
void k_gemm2(float* __restrict__ out) {
    int tile = blockIdx.x;
    if (tile >= g_ntiles) return;
    int e = g_tile_e[tile], row0 = g_tile_r0[tile], rend = g_tile_rend[tile];
    int n0 = blockIdx.y * 128;

    extern __shared__ __half dyn[];
    __half (*sA)[128][40] = (__half (*)[128][40])dyn;
    __half (*sB)[128][40] = (__half (*)[128][40])(dyn + 2 * 128 * 40);
    uint32_t smemB = s2u(dyn);

    __shared__ int   sTok[BM];
    __shared__ float sW[BM];
    int tid = threadIdx.x;
    if (tid < BM) {
        int r = row0 + tid;
        sTok[tid] = (r < rend) ? g_rowtok[r] : 0;
        sW[tid]   = (r < rend) ? g_roww[r] : 0.f;
    }
    __syncthreads();

    const __half* w2t = g_w2t + (size_t)e * D_DIM * F_DIM;
    int wid = tid >> 5, lane = tid & 31;
    int wm = (wid & 1) * 64, wn = (wid >> 1) * 32;

    uint32_t aoff = (((lane >> 3) & 1) * 8 + (lane & 7)) * 40 + (lane >> 4) * 8;
    uint32_t boff = ((lane >> 4) * 8 + (lane & 7)) * 40 + ((lane >> 3) & 1) * 8;

    int arow[2], ac[2];
    bool apred[2];
#pragma unroll
    for (int i = 0; i < 2; i++) {
        int id = i * 256 + tid;
        arow[i] = id >> 2; ac[i] = id & 3;
        apred[i] = (row0 + arow[i]) < rend;
    }

    auto issue = [&](int kt, int buf) {
#pragma unroll
        for (int i = 0; i < 2; i++)
            cp16p(&sA[buf][arow[i]][ac[i] * 8],
                  g_hh + (size_t)(row0 + arow[i]) * F_DIM + kt * BK + ac[i] * 8,
                  apred[i]);
#pragma unroll
        for (int i = 0; i < 2; i++) {
            int id = i * 256 + tid;
            int row = id >> 2, c = id & 3;
            cp16(&sB[buf][row][c * 8],
                 w2t + (size_t)(n0 + row) * F_DIM + kt * BK + c * 8);
        }
        cp_commit();
    };

    float acc[4][4][4];
#pragma unroll
    for (int i = 0; i < 4; i++)
#pragma unroll
        for (int j = 0; j < 4; j++)
#pragma unroll
            for (int k = 0; k < 4; k++) acc[i][j][k] = 0.f;

    const int NK = F_DIM / BK;             // 112
    issue(0, 0);

    for (int kt = 0; kt < NK; kt++) {
        int buf = kt & 1;
        if (kt + 1 < NK) { issue(kt + 1, (kt + 1) & 1); cp_wait<1>(); }
        else             { cp_wait<0>(); }
        __syncthreads();

#pragma unroll
        for (int ks = 0; ks < 2; ks++) {
            uint32_t a[4][4];
#pragma unroll
            for (int mf = 0; mf < 4; mf++)
                ldsm4(a[mf], smemB + (buf * 5120 +
                       (wm + mf * 16) * 40 + ks * 16 + aoff) * 2);
#pragma unroll
            for (int j = 0; j < 2; j++) {
                uint32_t b[4];
                ldsm4(b, smemB + 20480 + (buf * 5120 +
                       (n0 * 0 + wn + j * 16) * 40 + ks * 16 + boff) * 2);
#pragma unroll
                for (int mf = 0; mf < 4; mf++) {
                    mma_f16(acc[mf][2 * j],     a[mf][0], a[mf][1], a[mf][2], a[mf][3], b[0], b[1]);
                    mma_f16(acc[mf][2 * j + 1], a[mf][0], a[mf][1], a[mf][2], a[mf][3], b[2], b[3]);
                }
            }
        }
        __syncthreads();
    }

    // epilogue: out[tok, col] += weight * acc (exactly 2 adds/element -> deterministic)
#pragma unroll
    for (int mf = 0; mf < 4; mf++) {
#pragma unroll
        for (int half_ = 0; half_ < 2; half_++) {
            int rl = wm + mf * 16 + (lane >> 2) + half_ * 8;
            int r = row0 + rl;
            if (r < rend) {
                int tok = sTok[rl];
                float s = sW[rl];
                float* op = out + (size_t)tok * D_DIM;
#pragma unroll
                for (int nf = 0; nf < 4; nf++) {
                    int col = n0 + wn + nf * 8 + (lane & 3) * 2;
                    atomicAdd(op + col,     acc[mf][nf][half_ * 2] * s);
                    atomicAdd(op + col + 1, acc[mf][nf][half_ * 2 + 1] * s);
                }
            }
        }
    }
}

// ---------------- entry ----------------
extern "C" void kernel_launch(void* const* d_in, const int* in_sizes, int n_in,
                              void* d_out, int out_size) {
    const float* x  = (const float*)d_in[0];
    const float* gw = (const float*)d_in[1];
    const float* w1 = (const float*)d_in[2];
    const float* w3 = (const float*)d_in[3];
    const float* w2 = (const float*)d_in[4];

    float* out = (float*)d_out;
    float* logits = out + (size_t)T_TOK * D_DIM;

    static bool attr_set = false;
    if (!attr_set) {
        cudaFuncSetAttribute(k_gemm1, cudaFuncAttributeMaxDynamicSharedMemorySize, G1_SMEM);
        cudaFuncSetAttribute(k_gemm2, cudaFuncAttributeMaxDynamicSharedMemorySize, G2_SMEM);
        attr_set = true;
    }

    k_prep<<<87040, 256>>>(x, w1, w3, w2);              // launch 0
    k_router<<<T_TOK, 256>>>(x, gw, logits);            // launch 1
    k_scan_scatter<<<1, 256>>>();                       // launch 2
    dim3 g1(MAX_TILES, F_DIM / 64);
    k_gemm1<<<g1, 256, G1_SMEM>>>();                    // launch 3 <- ncu target
    k_zero<<<2048, 256>>>((float4*)out, (T_TOK * D_DIM) / 4);   // launch 4
    dim3 g2(MAX_TILES, D_DIM / 128);
    k_gemm2<<<g2, 256, G2_SMEM>>>(out);                 // launch 5
}

// round 11
// speedup vs baseline: 3.2359x; 1.1146x over previous
#include <cuda_runtime.h>
#include <cuda_fp16.h>
#include <cstdint>

#define T_TOK 8192
#define D_DIM 1024
#define F_DIM 3584
#define N_EXP 8
#define N_ASSIGN (T_TOK * 2)
#define BM 128
#define BK 64
#define MAX_TILES (N_ASSIGN / BM + N_EXP)  // 136

// ---------------- scratch (static __device__, allocation-free) ----------------
__device__ __half g_xh [(size_t)T_TOK * D_DIM];           // x, fp16 [t][d]
__device__ __half g_w1t[(size_t)N_EXP * F_DIM * D_DIM];   // w1^T fp16 [e][n][k]
__device__ __half g_w3t[(size_t)N_EXP * F_DIM * D_DIM];   // w3^T fp16 [e][n][k]
__device__ __half g_w2t[(size_t)N_EXP * D_DIM * F_DIM];   // w2^T fp16 [e][d][f]
__device__ __half g_hh [(size_t)N_ASSIGN * F_DIM];        // SwiGLU out, fp16
__device__ int   g_rowtok[N_ASSIGN];
__device__ float g_roww[N_ASSIGN];
__device__ int   g_route_e[N_ASSIGN];
__device__ float g_route_w[N_ASSIGN];
__device__ int   g_cnt[N_EXP];
__device__ int   g_off[N_EXP + 1];
__device__ int   g_tile_e[MAX_TILES];
__device__ int   g_tile_r0[MAX_TILES];
__device__ int   g_tile_rend[MAX_TILES];
__device__ int   g_ntiles;

// ---------------- helpers ----------------
__device__ __forceinline__ void mma_f16(float c[4], uint32_t a0, uint32_t a1,
                                        uint32_t a2, uint32_t a3,
                                        uint32_t b0, uint32_t b1) {
    asm volatile(
        "mma.sync.aligned.m16n8k16.row.col.f32.f16.f16.f32 "
        "{%0,%1,%2,%3}, {%4,%5,%6,%7}, {%8,%9}, {%0,%1,%2,%3};\n"
        : "+f"(c[0]), "+f"(c[1]), "+f"(c[2]), "+f"(c[3])
        : "r"(a0), "r"(a1), "r"(a2), "r"(a3), "r"(b0), "r"(b1));
}
__device__ __forceinline__ void ldsm4(uint32_t r[4], uint32_t addr) {
    asm volatile("ldmatrix.sync.aligned.m8n8.x4.shared.b16 {%0,%1,%2,%3}, [%4];"
        : "=r"(r[0]), "=r"(r[1]), "=r"(r[2]), "=r"(r[3]) : "r"(addr));
}
__device__ __forceinline__ uint32_t s2u(const void* p) {
    return (uint32_t)__cvta_generic_to_shared(p);
}
__device__ __forceinline__ void cp16(void* s, const void* g) {
    uint32_t sa = (uint32_t)__cvta_generic_to_shared(s);
    asm volatile("cp.async.cg.shared.global [%0], [%1], 16;\n" :: "r"(sa), "l"(g));
}
__device__ __forceinline__ void cp16p(void* s, const void* g, bool p) {
    uint32_t sa = (uint32_t)__cvta_generic_to_shared(s);
    int b = p ? 16 : 0;
    asm volatile("cp.async.cg.shared.global [%0], [%1], 16, %2;\n" :: "r"(sa), "l"(g), "r"(b));
}
__device__ __forceinline__ void cp_commit() {
    asm volatile("cp.async.commit_group;\n" ::: "memory");
}
template <int N>
__device__ __forceinline__ void cp_wait() {
    asm volatile("cp.async.wait_group %0;\n" :: "n"(N) : "memory");
}

// ---------------- prepass: convert/transpose everything to fp16 ----------------
__global__ void k_prep(const float* __restrict__ x,  const float* __restrict__ w1,
                       const float* __restrict__ w3, const float* __restrict__ w2) {
    __shared__ float t[32][33];
    int bid = blockIdx.x, tid = threadIdx.x;
    if (bid < 86016) {
        int which = bid / 28672;
        int r = bid % 28672;
        const float* src; __half* dst; int K, N;
        if (which == 0)      { src = w1; dst = g_w1t; K = D_DIM; N = F_DIM; }
        else if (which == 1) { src = w3; dst = g_w3t; K = D_DIM; N = F_DIM; }
        else                 { src = w2; dst = g_w2t; K = F_DIM; N = D_DIM; }
        int per_e = (K / 32) * (N / 32);           // 3584
        int e = r / per_e, rr = r % per_e;
        int nt = rr % (N / 32), kt = rr / (N / 32);
        int n0 = nt * 32, k0 = kt * 32;
        int tx = tid & 31, ty = tid >> 5;
        const float* s = src + (size_t)e * K * N;
        __half* d = dst + (size_t)e * N * K;
        for (int i = ty; i < 32; i += 8)
            t[i][tx] = s[(size_t)(k0 + i) * N + n0 + tx];
        __syncthreads();
        for (int i = ty; i < 32; i += 8)
            d[(size_t)(n0 + i) * K + k0 + tx] = __float2half_rn(t[tx][i]);
    } else {
        int base = (bid - 86016) * 8192;
        for (int j = tid; j < 8192; j += 256)
            g_xh[base + j] = __float2half_rn(x[base + j]);
    }
}

// ---------------- router ----------------
__global__ void k_router(const float* __restrict__ x, const float* __restrict__ gw,
                         float* __restrict__ logits_out) {
    int t = blockIdx.x, tid = threadIdx.x;
    const float* xr = x + (size_t)t * D_DIM;
    float acc[N_EXP];
#pragma unroll
    for (int e = 0; e < N_EXP; e++) acc[e] = 0.f;
    for (int j = tid; j < D_DIM; j += 256) {
        float xv = xr[j];
#pragma unroll
        for (int e = 0; e < N_EXP; e++) acc[e] += xv * gw[e * D_DIM + j];
    }
#pragma unroll
    for (int e = 0; e < N_EXP; e++)
#pragma unroll
        for (int o = 16; o > 0; o >>= 1)
            acc[e] += __shfl_xor_sync(0xffffffffu, acc[e], o);
    __shared__ float wsum[8][N_EXP];
    __shared__ float sl[N_EXP];
    int wid = tid >> 5, lane = tid & 31;
    if (lane == 0)
#pragma unroll
        for (int e = 0; e < N_EXP; e++) wsum[wid][e] = acc[e];
    __syncthreads();
    if (tid < N_EXP) {
        float s = 0.f;
#pragma unroll
        for (int w = 0; w < 8; w++) s += wsum[w][tid];
        sl[tid] = s;
        logits_out[(size_t)t * N_EXP + tid] = s;
    }
    __syncthreads();
    if (tid == 0) {
        float l[N_EXP];
#pragma unroll
        for (int e = 0; e < N_EXP; e++) l[e] = sl[e];
        int i0 = 0;
#pragma unroll
        for (int e = 1; e < N_EXP; e++) if (l[e] > l[i0]) i0 = e;
        int i1 = (i0 == 0) ? 1 : 0;
#pragma unroll
        for (int e = 0; e < N_EXP; e++) if (e != i0 && l[e] > l[i1]) i1 = e;
        float r = __expf(l[i1] - l[i0]);
        g_route_e[2 * t] = i0;     g_route_w[2 * t] = 1.f / (1.f + r);
        g_route_e[2 * t + 1] = i1; g_route_w[2 * t + 1] = r / (1.f + r);
        atomicAdd(&g_cnt[i0], 1);
        atomicAdd(&g_cnt[i1], 1);
    }
}

// ---------------- scan + scatter, one block ----------------
__global__ void k_scan_scatter() {
    __shared__ int scur[N_EXP];
    int tid = threadIdx.x;
    if (tid == 0) {
        int off = 0;
        for (int e = 0; e < N_EXP; e++) { g_off[e] = off; off += g_cnt[e]; }
        g_off[N_EXP] = off;
        int nt = 0;
        for (int e = 0; e < N_EXP; e++) {
            int c = g_cnt[e], r0 = g_off[e];
            for (int i = 0; i < (c + BM - 1) / BM; i++) {
                g_tile_e[nt] = e; g_tile_r0[nt] = r0 + i * BM; g_tile_rend[nt] = r0 + c; nt++;
            }
        }
        g_ntiles = nt;
        for (int e = 0; e < N_EXP; e++) g_cnt[e] = 0;
    }
    if (tid < N_EXP) scur[tid] = 0;
    __syncthreads();
    for (int t = tid; t < T_TOK; t += 256) {
#pragma unroll
        for (int k = 0; k < 2; k++) {
            int e = g_route_e[2 * t + k];
            int p = g_off[e] + atomicAdd(&scur[e], 1);
            g_rowtok[p] = t;
            g_roww[p] = g_route_w[2 * t + k];
        }
    }
}

__global__ void k_zero(float4* p, int n4) {
    int stride = gridDim.x * blockDim.x;
    for (int i = blockIdx.x * blockDim.x + threadIdx.x; i < n4; i += stride)
        p[i] = make_float4(0.f, 0.f, 0.f, 0.f);
}

// ---------------- GEMM1: H = silu(Xg@W1) * (Xg@W3), fp16 + ldmatrix, BK=64 ----------------
// halves: A[2][128][72] = 18432, B[2][2][64][72] = 18432 -> 73728 bytes total
#define G1_SMEM 73728
#define ASTG1 9216            // halves per A stage
#define BBASE1 18432          // halves, start of B region
__global__ __launch_bounds__(256, 2)
void k_gemm1() {
    int tile = blockIdx.x;
    if (tile >= g_ntiles) return;
    int e = g_tile_e[tile], row0 = g_tile_r0[tile], rend = g_tile_rend[tile];
    int n0 = blockIdx.y * 64;

    extern __shared__ __half dyn[];
    uint32_t smemB = s2u(dyn);

    __shared__ int sTok[BM];
    int tid = threadIdx.x;
    if (tid < BM) {
        int r = row0 + tid;
        sTok[tid] = (r < rend) ? g_rowtok[r] : -1;
    }
    __syncthreads();

    const __half* w1t = g_w1t + (size_t)e * F_DIM * D_DIM;
    const __half* w3t = g_w3t + (size_t)e * F_DIM * D_DIM;

    int wid = tid >> 5, lane = tid & 31;
    int wm = (wid & 3) * 32, wn = (wid >> 2) * 32;

    // ldmatrix per-lane offsets (halves), row stride 72
    uint32_t aoff = (((lane >> 3) & 1) * 8 + (lane & 7)) * 72 + (lane >> 4) * 8;
    uint32_t boff = ((lane >> 4) * 8 + (lane & 7)) * 72 + ((lane >> 3) & 1) * 8;

    // staging coords: 4 A-chunks + 4 B-chunks per thread (1024 chunks each)
    int arow[4], ac[4];
    const __half* asrc[4];
    bool apred[4];
#pragma unroll
    for (int i = 0; i < 4; i++) {
        int id = i * 256 + tid;            // 0..1023
        arow[i] = id >> 3; ac[i] = id & 7;
        int tok = sTok[arow[i]];
        asrc[i] = g_xh + (size_t)(tok < 0 ? 0 : tok) * D_DIM + ac[i] * 8;
        apred[i] = (tok >= 0);
    }

    auto issue = [&](int kt, int buf) {
        __half* sA = dyn + buf * ASTG1;
        __half* sB = dyn + BBASE1 + buf * 2 * 4608;
#pragma unroll
        for (int i = 0; i < 4; i++)
            cp16p(sA + arow[i] * 72 + ac[i] * 8, asrc[i] + kt * BK, apred[i]);
#pragma unroll
        for (int i = 0; i < 4; i++) {
            int id = i * 256 + tid;
            int mat = id >> 9, rem = id & 511;
            int row = rem >> 3, c = rem & 7;
            const __half* wt = mat ? w3t : w1t;
            cp16(sB + mat * 4608 + row * 72 + c * 8,
                 wt + (size_t)(n0 + row) * D_DIM + kt * BK + c * 8);
        }
        cp_commit();
    };

    float accP[2][4][4], accQ[2][4][4];
#pragma unroll
    for (int i = 0; i < 2; i++)
#pragma unroll
        for (int j = 0; j < 4; j++)
#pragma unroll
            for (int k = 0; k < 4; k++) { accP[i][j][k] = 0.f; accQ[i][j][k] = 0.f; }

    const int NK = D_DIM / BK;             // 16
    issue(0, 0);

    for (int kt = 0; kt < NK; kt++) {
        int buf = kt & 1;
        if (kt + 1 < NK) { issue(kt + 1, (kt + 1) & 1); cp_wait<1>(); }
        else             { cp_wait<0>(); }
        __syncthreads();

#pragma unroll
        for (int ks = 0; ks < 4; ks++) {
            uint32_t a[2][4];
#pragma unroll
            for (int mf = 0; mf < 2; mf++)
                ldsm4(a[mf], smemB + (buf * ASTG1 +
                       (wm + mf * 16) * 72 + ks * 16 + aoff) * 2);
#pragma unroll
            for (int mat = 0; mat < 2; mat++) {
#pragma unroll
                for (int j = 0; j < 2; j++) {
                    uint32_t b[4];
                    ldsm4(b, smemB + (BBASE1 + (buf * 2 + mat) * 4608 +
                           (wn + j * 16) * 72 + ks * 16 + boff) * 2);
#pragma unroll
                    for (int mf = 0; mf < 2; mf++) {
                        float* c0 = mat ? accQ[mf][2 * j]     : accP[mf][2 * j];
                        float* c1 = mat ? accQ[mf][2 * j + 1] : accP[mf][2 * j + 1];
                        mma_f16(c0, a[mf][0], a[mf][1], a[mf][2], a[mf][3], b[0], b[1]);
                        mma_f16(c1, a[mf][0], a[mf][1], a[mf][2], a[mf][3], b[2], b[3]);
                    }
                }
            }
        }
        __syncthreads();
    }

    // epilogue: h = silu(p) * q -> fp16 pair store
#pragma unroll
    for (int mf = 0; mf < 2; mf++) {
#pragma unroll
        for (int half_ = 0; half_ < 2; half_++) {
            int rl = wm + mf * 16 + (lane >> 2) + half_ * 8;
            int r = row0 + rl;
            if (r < rend) {
#pragma unroll
                for (int nf = 0; nf < 4; nf++) {
                    int col = n0 + wn + nf * 8 + (lane & 3) * 2;
                    float p0 = accP[mf][nf][half_ * 2], p1 = accP[mf][nf][half_ * 2 + 1];
                    float q0 = accQ[mf][nf][half_ * 2], q1 = accQ[mf][nf][half_ * 2 + 1];
                    float h0 = (p0 / (1.f + __expf(-p0))) * q0;
                    float h1 = (p1 / (1.f + __expf(-p1))) * q1;
                    __half2 hv; hv.x = __float2half_rn(h0); hv.y = __float2half_rn(h1);
                    *(__half2*)(g_hh + (size_t)r * F_DIM + col) = hv;
                }
            }
        }
    }
}

// ---------------- GEMM2: Y = H @ W2[e], fp16 + ldmatrix, BK=64, scatter-add ----------------
// halves: A[2][128][72] = 18432, B[2][128][72] = 18432 -> 73728 bytes
#define G2_SMEM 73728
#define ASTG2 9216
#define BBASE2 18432
__global__ __launch_bounds__(256, 2)
void k_gemm2(float* __restrict__ out) {
    int tile = blockIdx.x;
    if (tile >= g_ntiles) return;
    int e = g_tile_e[tile], row0 = g_tile_r0[tile], rend = g_tile_rend[tile];
    int n0 = blockIdx.y * 128;

    extern __shared__ __half dyn[];
    uint32_t smemB = s2u(dyn);

    __shared__ int   sTok[BM];
    __shared__ float sW[BM];
    int tid = threadIdx.x;
    if (tid < BM) {
        int r = row0 + tid;
        sTok[tid] = (r < rend) ? g_rowtok[r] : 0;
        sW[tid]   = (r < rend) ? g_roww[r] : 0.f;
    }
    __syncthreads();

    const __half* w2t = g_w2t + (size_t)e * D_DIM * F_DIM;
    int wid = tid >> 5, lane = tid & 31;
    int wm = (wid & 1) * 64, wn = (wid >> 1) * 32;

    uint32_t aoff = (((lane >> 3) & 1) * 8 + (lane & 7)) * 72 + (lane >> 4) * 8;
    uint32_t boff = ((lane >> 4) * 8 + (lane & 7)) * 72 + ((lane >> 3) & 1) * 8;

    int arow[4], ac[4];
    bool apred[4];
#pragma unroll
    for (int i = 0; i < 4; i++) {
        int id = i * 256 + tid;
        arow[i] = id >> 3; ac[i] = id & 7;
        apred[i] = (row0 + arow[i]) < rend;
    }

    auto issue = [&](int kt, int buf) {
        __half* sA = dyn + buf * ASTG2;
        __half* sB = dyn + BBASE2 + buf * ASTG2;
#pragma unroll
        for (int i = 0; i < 4; i++)
            cp16p(sA + arow[i] * 72 + ac[i] * 8,
                  g_hh + (size_t)(row0 + arow[i]) * F_DIM + kt * BK + ac[i] * 8,
                  apred[i]);
#pragma unroll
        for (int i = 0; i < 4; i++) {
            int id = i * 256 + tid;
            int row = id >> 3, c = id & 7;
            cp16(sB + row * 72 + c * 8,
                 w2t + (size_t)(n0 + row) * F_DIM + kt * BK + c * 8);
        }
        cp_commit();
    };

    float acc[4][4][4];
#pragma unroll
    for (int i = 0; i < 4; i++)
#pragma unroll
        for (int j = 0; j < 4; j++)
#pragma unroll
            for (int k = 0; k < 4; k++) acc[i][j][k] = 0.f;

    const int NK = F_DIM / BK;             // 56
    issue(0, 0);

    for (int kt = 0; kt < NK; kt++) {
        int buf = kt & 1;
        if (kt + 1 < NK) { issue(kt + 1, (kt + 1) & 1); cp_wait<1>(); }
        else             { cp_wait<0>(); }
        __syncthreads();

#pragma unroll
        for (int ks = 0; ks < 4; ks++) {
            uint32_t a[4][4];
#pragma unroll
            for (int mf = 0; mf < 4; mf++)
                ldsm4(a[mf], smemB + (buf * ASTG2 +
                       (wm + mf * 16) * 72 + ks * 16 + aoff) * 2);
#pragma unroll
            for (int j = 0; j < 2; j++) {
                uint32_t b[4];
                ldsm4(b, smemB + (BBASE2 + buf * ASTG2 +
                       (wn + j * 16) * 72 + ks * 16 + boff) * 2);
#pragma unroll
                for (int mf = 0; mf < 4; mf++) {
                    mma_f16(acc[mf][2 * j],     a[mf][0], a[mf][1], a[mf][2], a[mf][3], b[0], b[1]);
                    mma_f16(acc[mf][2 * j + 1], a[mf][0], a[mf][1], a[mf][2], a[mf][3], b[2], b[3]);
                }
            }
        }
        __syncthreads();
    }

    // epilogue: out[tok, col] += weight * acc (exactly 2 adds/element -> deterministic)
#pragma unroll
    for (int mf = 0; mf < 4; mf++) {
#pragma unroll
        for (int half_ = 0; half_ < 2; half_++) {
            int rl = wm + mf * 16 + (lane >> 2) + half_ * 8;
            int r = row0 + rl;
            if (r < rend) {
                int tok = sTok[rl];
                float s = sW[rl];
                float* op = out + (size_t)tok * D_DIM;
#pragma unroll
                for (int nf = 0; nf < 4; nf++) {
                    int col = n0 + wn + nf * 8 + (lane & 3) * 2;
                    atomicAdd(op + col,     acc[mf][nf][half_ * 2] * s);
                    atomicAdd(op + col + 1, acc[mf][nf][half_ * 2 + 1] * s);
                }
            }
        }
    }
}

// ---------------- entry ----------------
extern "C" void kernel_launch(void* const* d_in, const int* in_sizes, int n_in,
                              void* d_out, int out_size) {
    const float* x  = (const float*)d_in[0];
    const float* gw = (const float*)d_in[1];
    const float* w1 = (const float*)d_in[2];
    const float* w3 = (const float*)d_in[3];
    const float* w2 = (const float*)d_in[4];

    float* out = (float*)d_out;
    float* logits = out + (size_t)T_TOK * D_DIM;

    static bool attr_set = false;
    if (!attr_set) {
        cudaFuncSetAttribute(k_gemm1, cudaFuncAttributeMaxDynamicSharedMemorySize, G1_SMEM);
        cudaFuncSetAttribute(k_gemm2, cudaFuncAttributeMaxDynamicSharedMemorySize, G2_SMEM);
        attr_set = true;
    }

    k_prep<<<87040, 256>>>(x, w1, w3, w2);              // launch 0
    k_router<<<T_TOK, 256>>>(x, gw, logits);            // launch 1
    k_scan_scatter<<<1, 256>>>();                       // launch 2
    dim3 g1(MAX_TILES, F_DIM / 64);
    k_gemm1<<<g1, 256, G1_SMEM>>>();                    // launch 3 <- ncu target
    k_zero<<<2048, 256>>>((float4*)out, (T_TOK * D_DIM) / 4);   // launch 4
    dim3 g2(MAX_TILES, D_DIM / 128);
    k_gemm2<<<g2, 256, G2_SMEM>>>(out);                 // launch 5
}